// round 10
// baseline (speedup 1.0000x reference)
#include <cuda_runtime.h>

// Fixed problem dims
#define NB 4
#define NQv 512
#define MMv 512
#define DDv 256
#define HHv 256

// Scratch (device globals: no allocations allowed)
__device__ float    g_q[NB * NQv * HHv];     // projected q, [b*NQ+n][h]
__device__ unsigned g_kTh[NB * HHv * MMv];   // projected k, transposed, packed half2(k,k)
__device__ float    g_sc[NB * NQv * MMv];    // raw scores [b][n][m]

__device__ __forceinline__ float fex2(float x) {
    float y; asm("ex2.approx.f32 %0, %1;" : "=f"(y) : "f"(x)); return y;
}
__device__ __forceinline__ unsigned long long pk2(float a, float b) {
    unsigned long long r; asm("mov.b64 %0, {%1, %2};" : "=l"(r) : "f"(a), "f"(b)); return r;
}
__device__ __forceinline__ void fma2(unsigned long long &d, unsigned long long a, unsigned long long b) {
    asm("fma.rn.f32x2 %0, %1, %2, %0;" : "+l"(d) : "l"(a), "l"(b));
}
__device__ __forceinline__ float2 up2(unsigned long long v) {
    float2 r; asm("mov.b64 {%0, %1}, %2;" : "=f"(r.x), "=f"(r.y) : "l"(v)); return r;
}
__device__ __forceinline__ unsigned packh2(float lo, float hi) {
    unsigned r; asm("cvt.rn.f16x2.f32 %0, %1, %2;" : "=r"(r) : "f"(hi), "f"(lo)); return r;
}
__device__ __forceinline__ unsigned hadd2(unsigned a, unsigned b) {
    unsigned r; asm("add.f16x2 %0, %1, %2;" : "=r"(r) : "r"(a), "r"(b)); return r;
}
__device__ __forceinline__ unsigned htanh2(unsigned a) {
    unsigned r; asm("tanh.approx.f16x2 %0, %1;" : "=r"(r) : "r"(a)); return r;
}
__device__ __forceinline__ unsigned hfma2(unsigned a, unsigned b, unsigned c) {
    unsigned r; asm("fma.rn.f16x2 %0, %1, %2, %3;" : "=r"(r) : "r"(a), "r"(b), "r"(c)); return r;
}
__device__ __forceinline__ void drain2(unsigned p, float &f0, float &f1) {
    unsigned short lo, hi; float a, b;
    asm("mov.b32 {%0, %1}, %2;" : "=h"(lo), "=h"(hi) : "r"(p));
    asm("cvt.f32.f16 %0, %1;" : "=f"(a) : "h"(lo));
    asm("cvt.f32.f16 %0, %1;" : "=f"(b) : "h"(hi));
    f0 += a; f1 += b;
}

// ---------------------------------------------------------------------------
// Per-batch projection GEMM: grid 64 (32 q-tile blocks + 32 kT-tile blocks).
// 64x64 tile, 256 threads, 4x4 micro-tile, f32x2 FMAs, double-buffered (R6).
// ---------------------------------------------------------------------------
__global__ __launch_bounds__(256) void proj_kernel(const float* __restrict__ query,
                                                   const float* __restrict__ key,
                                                   const float* __restrict__ Wq,
                                                   const float* __restrict__ Wk,
                                                   int b)
{
    __shared__ __align__(16) float As[16][68];
    __shared__ __align__(16) float Bs[16][64];

    int bid = blockIdx.x;
    int is_k = bid >> 5;
    int local = bid & 31;
    int row0 = (local >> 2) * 64;     // row within batch [0,512)
    int col0 = (local & 3) * 64;
    const float* A = (is_k ? key : query) + (b * MMv) * DDv;
    const float* B = is_k ? Wk : Wq;

    int t = threadIdx.x;
    int tx = t & 15, ty = t >> 4;
    int arow = t >> 2, akq = t & 3;
    int bk = t >> 4, bh = t & 15;

    const float* Aptr = A + (row0 + arow) * DDv + akq * 4;
    const float* Bptr = B + bk * HHv + col0 + bh * 4;

    unsigned long long acc[4][2];
#pragma unroll
    for (int i = 0; i < 4; i++) { acc[i][0] = 0ull; acc[i][1] = 0ull; }

    float4 a_n = *(const float4*)(Aptr);
    float4 b_n = *(const float4*)(Bptr);

    for (int k0 = 0; k0 < DDv; k0 += 16) {
        As[akq * 4 + 0][arow] = a_n.x;
        As[akq * 4 + 1][arow] = a_n.y;
        As[akq * 4 + 2][arow] = a_n.z;
        As[akq * 4 + 3][arow] = a_n.w;
        *(float4*)&Bs[bk][bh * 4] = b_n;
        __syncthreads();

        if (k0 + 16 < DDv) {
            a_n = *(const float4*)(Aptr + k0 + 16);
            b_n = *(const float4*)(Bptr + (k0 + 16) * HHv);
        }

#pragma unroll
        for (int k = 0; k < 16; k++) {
            const unsigned long long* br = (const unsigned long long*)&Bs[k][tx * 4];
            unsigned long long b0 = br[0], b1 = br[1];
#pragma unroll
            for (int i = 0; i < 4; i++) {
                float a = As[k][ty * 4 + i];
                unsigned long long aa = pk2(a, a);
                fma2(acc[i][0], aa, b0);
                fma2(acc[i][1], aa, b1);
            }
        }
        __syncthreads();
    }

#pragma unroll
    for (int i = 0; i < 4; i++) {
        int row = row0 + ty * 4 + i;   // within batch
        int col = col0 + tx * 4;
        float2 c0 = up2(acc[i][0]);
        float2 c1 = up2(acc[i][1]);
        if (!is_k) {
            *(float4*)(g_q + (b * NQv + row) * HHv + col) =
                make_float4(c0.x, c0.y, c1.x, c1.y);
        } else {
            unsigned* base = g_kTh + (b * HHv) * MMv + row;   // m = row
            base[(col + 0) * MMv] = packh2(c0.x, c0.x);
            base[(col + 1) * MMv] = packh2(c0.y, c0.y);
            base[(col + 2) * MMv] = packh2(c1.x, c1.x);
            base[(col + 3) * MMv] = packh2(c1.y, c1.y);
        }
    }
}

// ---------------------------------------------------------------------------
// Per-batch score kernel (R9 all-f16x2 body, MUFU elem-rate bound):
// grid 256 = qc(64) x mc(4); 128 threads; tile (8q x 128m).
// ---------------------------------------------------------------------------
__global__ __launch_bounds__(128) void score_kernel(const float* __restrict__ Wv, int b)
{
    __shared__ __align__(16) uint4 qsh[HHv];
    __shared__ __align__(16) unsigned wsh[HHv];

    int t = threadIdx.x;
    int bid = blockIdx.x;
    int mc = bid & 3;
    int qc = bid >> 2;
    int n0 = qc * 8;
    int m = mc * 128 + t;

    {
        const float* qb = g_q + (b * NQv + n0) * HHv + 2 * t;
        float2 r[8];
#pragma unroll
        for (int q = 0; q < 8; q++)
            r[q] = *(const float2*)(qb + q * HHv);
#pragma unroll
        for (int j = 0; j < 2; j++) {
            int h = 2 * t + j;
            float v0 = j ? r[0].y : r[0].x, v1 = j ? r[1].y : r[1].x;
            float v2 = j ? r[2].y : r[2].x, v3 = j ? r[3].y : r[3].x;
            float v4 = j ? r[4].y : r[4].x, v5 = j ? r[5].y : r[5].x;
            float v6 = j ? r[6].y : r[6].x, v7 = j ? r[7].y : r[7].x;
            qsh[h] = make_uint4(packh2(v0, v1), packh2(v2, v3),
                                packh2(v4, v5), packh2(v6, v7));
        }
        float2 wv = *(const float2*)(Wv + 2 * t);
        wsh[2 * t + 0] = packh2(wv.x, wv.x);
        wsh[2 * t + 1] = packh2(wv.y, wv.y);
    }
    __syncthreads();

    float facc[8];
#pragma unroll
    for (int q = 0; q < 8; q++) facc[q] = 0.f;

    const unsigned* kb = g_kTh + (b * HHv) * MMv + m;

    for (int h0 = 0; h0 < HHv; h0 += 8) {
        unsigned acc2[4] = {0u, 0u, 0u, 0u};
#pragma unroll
        for (int hh = 0; hh < 8; hh++) {
            int h = h0 + hh;
            unsigned kk2 = kb[h * MMv];
            uint4 qh = qsh[h];
            unsigned w2 = wsh[h];
            acc2[0] = hfma2(w2, htanh2(hadd2(qh.x, kk2)), acc2[0]);
            acc2[1] = hfma2(w2, htanh2(hadd2(qh.y, kk2)), acc2[1]);
            acc2[2] = hfma2(w2, htanh2(hadd2(qh.z, kk2)), acc2[2]);
            acc2[3] = hfma2(w2, htanh2(hadd2(qh.w, kk2)), acc2[3]);
        }
        drain2(acc2[0], facc[0], facc[1]);
        drain2(acc2[1], facc[2], facc[3]);
        drain2(acc2[2], facc[4], facc[5]);
        drain2(acc2[3], facc[6], facc[7]);
    }

#pragma unroll
    for (int q = 0; q < 8; q++)
        g_sc[(b * NQv + n0 + q) * MMv + m] = facc[q];
}

// ---------------------------------------------------------------------------
// Per-batch softmax + AV, 16 queries/block: grid 32, 256 threads.
// Halves L2 value traffic vs 8q (64MB total). ps[] overlaid on sc[].
// ---------------------------------------------------------------------------
__global__ __launch_bounds__(256) void softav_kernel(const float* __restrict__ value,
                                                     float* __restrict__ out, int b)
{
    __shared__ __align__(16) float sc[16][MMv];   // 32KB; overlaid by ps after AV
    __shared__ float inv_s[16];
    float2 (*ps)[128] = (float2(*)[128])sc;       // [32][128]: [mg*16+q][vg]

    int t = threadIdx.x;
    int n0 = (int)blockIdx.x * 16;
    int w = t >> 5, lane = t & 31;

    // ---- Softmax: warp w handles rows 2w, 2w+1 ----
#pragma unroll
    for (int r = 0; r < 2; r++) {
        int row = 2 * w + r;
        const float* srow = g_sc + (b * NQv + n0 + row) * MMv;
        float vals[16];
        float vmax = -1e30f;
#pragma unroll
        for (int j = 0; j < 16; j++) {
            vals[j] = srow[lane + j * 32];
            vmax = fmaxf(vmax, vals[j]);
        }
#pragma unroll
        for (int o = 16; o > 0; o >>= 1)
            vmax = fmaxf(vmax, __shfl_xor_sync(0xffffffffu, vmax, o));
        float sum = 0.f;
#pragma unroll
        for (int j = 0; j < 16; j++) {
            float p = fex2((vals[j] - vmax) * 1.4426950408889634f);
            sc[row][lane + j * 32] = p;
            sum += p;
        }
#pragma unroll
        for (int o = 16; o > 0; o >>= 1)
            sum += __shfl_xor_sync(0xffffffffu, sum, o);
        if (lane == 0) inv_s[row] = 1.0f / sum;
    }
    __syncthreads();

    // ---- AV: m-split 2, thread owns v-pair vg, 16 q accumulators ----
    int mg = t >> 7;
    int vg = t & 127;
    const float* vbase = value + (b * MMv + mg * 256) * DDv + vg * 2;
    unsigned long long acc[16];
#pragma unroll
    for (int q = 0; q < 16; q++) acc[q] = 0ull;

    for (int m4 = 0; m4 < 256; m4 += 4) {
        float2 v0 = *(const float2*)(vbase + (m4 + 0) * DDv);
        float2 v1 = *(const float2*)(vbase + (m4 + 1) * DDv);
        float2 v2 = *(const float2*)(vbase + (m4 + 2) * DDv);
        float2 v3 = *(const float2*)(vbase + (m4 + 3) * DDv);
        unsigned long long w0 = pk2(v0.x, v0.y);
        unsigned long long w1 = pk2(v1.x, v1.y);
        unsigned long long w2 = pk2(v2.x, v2.y);
        unsigned long long w3 = pk2(v3.x, v3.y);
        int mIdx = mg * 256 + m4;
#pragma unroll
        for (int q = 0; q < 16; q++) {
            float4 p = *(const float4*)&sc[q][mIdx];
            fma2(acc[q], pk2(p.x, p.x), w0);
            fma2(acc[q], pk2(p.y, p.y), w1);
            fma2(acc[q], pk2(p.z, p.z), w2);
            fma2(acc[q], pk2(p.w, p.w), w3);
        }
    }
    __syncthreads();   // all reads of sc done; overlay ps
#pragma unroll
    for (int q = 0; q < 16; q++) ps[mg * 16 + q][vg] = up2(acc[q]);
    __syncthreads();

    // Reduce 2 m-partials, scale, write out: 16q x 128 f2 = 2048 over 256 thr
#pragma unroll
    for (int r = 0; r < 8; r++) {
        int p = t + r * 256;
        int q = p >> 7, v2i = p & 127;
        float2 s0 = ps[q][v2i];
        float2 s1 = ps[16 + q][v2i];
        float iv = inv_s[q];
        ((float2*)out)[(b * NQv + n0 + q) * 128 + v2i] =
            make_float2((s0.x + s1.x) * iv, (s0.y + s1.y) * iv);
    }
}

// ---------------------------------------------------------------------------
// Streams/events created once in static init (host-side objects, before the
// harness's device-memory checkpoints). Fork-join pattern is graph-capturable.
// ---------------------------------------------------------------------------
struct PipeCtx {
    cudaStream_t sP, sS, sA;
    cudaEvent_t eFork, eP[NB], eS[NB], eEnd;
    PipeCtx() {
        cudaStreamCreateWithFlags(&sP, cudaStreamNonBlocking);
        cudaStreamCreateWithFlags(&sS, cudaStreamNonBlocking);
        cudaStreamCreateWithFlags(&sA, cudaStreamNonBlocking);
        cudaEventCreateWithFlags(&eFork, cudaEventDisableTiming);
        for (int i = 0; i < NB; i++) {
            cudaEventCreateWithFlags(&eP[i], cudaEventDisableTiming);
            cudaEventCreateWithFlags(&eS[i], cudaEventDisableTiming);
        }
        cudaEventCreateWithFlags(&eEnd, cudaEventDisableTiming);
    }
};
static PipeCtx g_pipe;

extern "C" void kernel_launch(void* const* d_in, const int* in_sizes, int n_in,
                              void* d_out, int out_size)
{
    const float* query = (const float*)d_in[0];
    const float* key   = (const float*)d_in[1];
    const float* value = (const float*)d_in[2];
    const float* Wq    = (const float*)d_in[3];
    const float* Wk    = (const float*)d_in[4];
    const float* Wv    = (const float*)d_in[5];
    float* out = (float*)d_out;

    // Fork from the captured (default) stream
    cudaEventRecord(g_pipe.eFork, 0);
    cudaStreamWaitEvent(g_pipe.sP, g_pipe.eFork, 0);

    // Diagonal pipeline: proj_b -> score_b -> softav_b, batches overlapped
    for (int b = 0; b < NB; b++) {
        proj_kernel<<<64, 256, 0, g_pipe.sP>>>(query, key, Wq, Wk, b);
        cudaEventRecord(g_pipe.eP[b], g_pipe.sP);
    }
    for (int b = 0; b < NB; b++) {
        cudaStreamWaitEvent(g_pipe.sS, g_pipe.eP[b], 0);
        score_kernel<<<256, 128, 0, g_pipe.sS>>>(Wv, b);
        cudaEventRecord(g_pipe.eS[b], g_pipe.sS);
    }
    for (int b = 0; b < NB; b++) {
        cudaStreamWaitEvent(g_pipe.sA, g_pipe.eS[b], 0);
        softav_kernel<<<32, 256, 0, g_pipe.sA>>>(value, out, b);
    }

    // Join back into the captured stream
    cudaEventRecord(g_pipe.eEnd, g_pipe.sA);
    cudaStreamWaitEvent(0, g_pipe.eEnd, 0);
}

// round 11
// speedup vs baseline: 1.4318x; 1.4318x over previous
#include <cuda_runtime.h>

// Fixed problem dims
#define NB 4
#define NQv 512
#define MMv 512
#define DDv 256
#define HHv 256

// Scratch (device globals: no allocations allowed)
__device__ float    g_q[NB * NQv * HHv];     // projected q, [b*NQ+n][h]
__device__ unsigned g_kTh[NB * HHv * MMv];   // projected k, transposed, packed half2(k,k)
__device__ float    g_sc[NB * NQv * MMv];    // raw scores [b][n][m]

__device__ __forceinline__ float fex2(float x) {
    float y; asm("ex2.approx.f32 %0, %1;" : "=f"(y) : "f"(x)); return y;
}
__device__ __forceinline__ unsigned long long pk2(float a, float b) {
    unsigned long long r; asm("mov.b64 %0, {%1, %2};" : "=l"(r) : "f"(a), "f"(b)); return r;
}
__device__ __forceinline__ void fma2(unsigned long long &d, unsigned long long a, unsigned long long b) {
    asm("fma.rn.f32x2 %0, %1, %2, %0;" : "+l"(d) : "l"(a), "l"(b));
}
__device__ __forceinline__ float2 up2(unsigned long long v) {
    float2 r; asm("mov.b64 {%0, %1}, %2;" : "=f"(r.x), "=f"(r.y) : "l"(v)); return r;
}
__device__ __forceinline__ unsigned packh2(float lo, float hi) {
    unsigned r; asm("cvt.rn.f16x2.f32 %0, %1, %2;" : "=r"(r) : "f"(hi), "f"(lo)); return r;
}
__device__ __forceinline__ unsigned hadd2(unsigned a, unsigned b) {
    unsigned r; asm("add.f16x2 %0, %1, %2;" : "=r"(r) : "r"(a), "r"(b)); return r;
}
__device__ __forceinline__ unsigned htanh2(unsigned a) {
    unsigned r; asm("tanh.approx.f16x2 %0, %1;" : "=r"(r) : "r"(a)); return r;
}
__device__ __forceinline__ unsigned hfma2(unsigned a, unsigned b, unsigned c) {
    unsigned r; asm("fma.rn.f16x2 %0, %1, %2, %3;" : "=r"(r) : "r"(a), "r"(b), "r"(c)); return r;
}
__device__ __forceinline__ void drain2(unsigned p, float &f0, float &f1) {
    unsigned short lo, hi; float a, b;
    asm("mov.b32 {%0, %1}, %2;" : "=h"(lo), "=h"(hi) : "r"(p));
    asm("cvt.f32.f16 %0, %1;" : "=f"(a) : "h"(lo));
    asm("cvt.f32.f16 %0, %1;" : "=f"(b) : "h"(hi));
    f0 += a; f1 += b;
}

// ---------------------------------------------------------------------------
// Combined projection GEMM: 256 blocks (128 q, 128 kT). 64x64 tile but now
// 512 THREADS (2 rows x 8 cols micro-tile): same LDS/LDG traffic, 2x the
// warps per SM (grid-starvation fix: occ 21% -> ~42%). Double-buffered.
// ---------------------------------------------------------------------------
__global__ __launch_bounds__(512) void proj_kernel(const float* __restrict__ query,
                                                   const float* __restrict__ key,
                                                   const float* __restrict__ Wq,
                                                   const float* __restrict__ Wk)
{
    __shared__ __align__(16) float As[16][68];
    __shared__ __align__(16) float Bs[16][64];

    int bid = blockIdx.x;
    int is_k = bid >> 7;
    int local = bid & 127;
    int row0 = (local >> 2) * 64;
    int col0 = (local & 3) * 64;
    const float* A = is_k ? key : query;
    const float* B = is_k ? Wk : Wq;

    int t = threadIdx.x;
    int tx = t & 15, ty = t >> 4;        // tx: 16 col-groups(4), ty: 32 row-groups(2)
    int arow = t >> 3, ak = (t & 7) * 2; // A load: 64 rows x 8 float2
    int bk = t >> 5, bh = (t & 31) * 2;  // B load: 16 rows x 32 float2

    const float* Aptr = A + (row0 + arow) * DDv + ak;
    const float* Bptr = B + bk * HHv + col0 + bh;

    unsigned long long acc[2][2];
    acc[0][0] = acc[0][1] = acc[1][0] = acc[1][1] = 0ull;

    float2 a_n = *(const float2*)(Aptr);
    float2 b_n = *(const float2*)(Bptr);

    for (int k0 = 0; k0 < DDv; k0 += 16) {
        As[ak + 0][arow] = a_n.x;
        As[ak + 1][arow] = a_n.y;
        Bs[bk][bh + 0] = b_n.x;
        Bs[bk][bh + 1] = b_n.y;
        __syncthreads();

        if (k0 + 16 < DDv) {
            a_n = *(const float2*)(Aptr + k0 + 16);
            b_n = *(const float2*)(Bptr + (k0 + 16) * HHv);
        }

#pragma unroll
        for (int k = 0; k < 16; k++) {
            const unsigned long long* br = (const unsigned long long*)&Bs[k][tx * 4];
            unsigned long long b0 = br[0], b1 = br[1];
            float a0 = As[k][ty * 2 + 0];
            float a1 = As[k][ty * 2 + 1];
            unsigned long long aa0 = pk2(a0, a0);
            unsigned long long aa1 = pk2(a1, a1);
            fma2(acc[0][0], aa0, b0);
            fma2(acc[0][1], aa0, b1);
            fma2(acc[1][0], aa1, b0);
            fma2(acc[1][1], aa1, b1);
        }
        __syncthreads();
    }

#pragma unroll
    for (int i = 0; i < 2; i++) {
        int row = row0 + ty * 2 + i;
        int col = col0 + tx * 4;
        float2 c0 = up2(acc[i][0]);
        float2 c1 = up2(acc[i][1]);
        if (!is_k) {
            *(float4*)(g_q + row * HHv + col) = make_float4(c0.x, c0.y, c1.x, c1.y);
        } else {
            int bb = row >> 9, m = row & 511;
            unsigned* base = g_kTh + (bb * HHv) * MMv + m;
            base[(col + 0) * MMv] = packh2(c0.x, c0.x);
            base[(col + 1) * MMv] = packh2(c0.y, c0.y);
            base[(col + 2) * MMv] = packh2(c1.x, c1.x);
            base[(col + 3) * MMv] = packh2(c1.y, c1.y);
        }
    }
}

// ---------------------------------------------------------------------------
// Score kernel (R9 all-f16x2 body, frozen at MUFU element-rate floor):
// tile (8q x 128m), 128 threads, grid 1024.
// ---------------------------------------------------------------------------
__global__ __launch_bounds__(128) void score_kernel(const float* __restrict__ Wv)
{
    __shared__ __align__(16) uint4 qsh[HHv];
    __shared__ __align__(16) unsigned wsh[HHv];

    int t = threadIdx.x;
    int bid = blockIdx.x;
    int mc = bid & 3;
    int qc = (bid >> 2) & 63;
    int b = bid >> 8;
    int n0 = qc * 8;
    int m = mc * 128 + t;

    {
        const float* qb = g_q + (b * NQv + n0) * HHv + 2 * t;
        float2 r[8];
#pragma unroll
        for (int q = 0; q < 8; q++)
            r[q] = *(const float2*)(qb + q * HHv);
#pragma unroll
        for (int j = 0; j < 2; j++) {
            int h = 2 * t + j;
            float v0 = j ? r[0].y : r[0].x, v1 = j ? r[1].y : r[1].x;
            float v2 = j ? r[2].y : r[2].x, v3 = j ? r[3].y : r[3].x;
            float v4 = j ? r[4].y : r[4].x, v5 = j ? r[5].y : r[5].x;
            float v6 = j ? r[6].y : r[6].x, v7 = j ? r[7].y : r[7].x;
            qsh[h] = make_uint4(packh2(v0, v1), packh2(v2, v3),
                                packh2(v4, v5), packh2(v6, v7));
        }
        float2 wv = *(const float2*)(Wv + 2 * t);
        wsh[2 * t + 0] = packh2(wv.x, wv.x);
        wsh[2 * t + 1] = packh2(wv.y, wv.y);
    }
    __syncthreads();

    float facc[8];
#pragma unroll
    for (int q = 0; q < 8; q++) facc[q] = 0.f;

    const unsigned* kb = g_kTh + (b * HHv) * MMv + m;

    for (int h0 = 0; h0 < HHv; h0 += 8) {
        unsigned acc2[4] = {0u, 0u, 0u, 0u};
#pragma unroll
        for (int hh = 0; hh < 8; hh++) {
            int h = h0 + hh;
            unsigned kk2 = kb[h * MMv];
            uint4 qh = qsh[h];
            unsigned w2 = wsh[h];
            acc2[0] = hfma2(w2, htanh2(hadd2(qh.x, kk2)), acc2[0]);
            acc2[1] = hfma2(w2, htanh2(hadd2(qh.y, kk2)), acc2[1]);
            acc2[2] = hfma2(w2, htanh2(hadd2(qh.z, kk2)), acc2[2]);
            acc2[3] = hfma2(w2, htanh2(hadd2(qh.w, kk2)), acc2[3]);
        }
        drain2(acc2[0], facc[0], facc[1]);
        drain2(acc2[1], facc[2], facc[3]);
        drain2(acc2[2], facc[4], facc[5]);
        drain2(acc2[3], facc[6], facc[7]);
    }

#pragma unroll
    for (int q = 0; q < 8; q++)
        g_sc[(b * NQv + n0 + q) * MMv + m] = facc[q];
}

// ---------------------------------------------------------------------------
// Softmax + AV, 16 queries/block (halves value L2 traffic to 64MB):
// grid 128 = 4b x 32 chunks, 256 threads. ps[] overlaid on sc[].
// ---------------------------------------------------------------------------
__global__ __launch_bounds__(256) void softav_kernel(const float* __restrict__ value,
                                                     float* __restrict__ out)
{
    __shared__ __align__(16) float sc[16][MMv];   // 32KB; overlaid by ps after AV
    __shared__ float inv_s[16];
    float2 (*ps)[128] = (float2(*)[128])sc;       // [32][128]: [mg*16+q][vg]

    int t = threadIdx.x;
    int b = (int)blockIdx.x >> 5;
    int n0 = ((int)blockIdx.x & 31) * 16;
    int w = t >> 5, lane = t & 31;

    // ---- Softmax: warp w handles rows 2w, 2w+1 ----
#pragma unroll
    for (int r = 0; r < 2; r++) {
        int row = 2 * w + r;
        const float* srow = g_sc + (b * NQv + n0 + row) * MMv;
        float vals[16];
        float vmax = -1e30f;
#pragma unroll
        for (int j = 0; j < 16; j++) {
            vals[j] = srow[lane + j * 32];
            vmax = fmaxf(vmax, vals[j]);
        }
#pragma unroll
        for (int o = 16; o > 0; o >>= 1)
            vmax = fmaxf(vmax, __shfl_xor_sync(0xffffffffu, vmax, o));
        float sum = 0.f;
#pragma unroll
        for (int j = 0; j < 16; j++) {
            float p = fex2((vals[j] - vmax) * 1.4426950408889634f);
            sc[row][lane + j * 32] = p;
            sum += p;
        }
#pragma unroll
        for (int o = 16; o > 0; o >>= 1)
            sum += __shfl_xor_sync(0xffffffffu, sum, o);
        if (lane == 0) inv_s[row] = 1.0f / sum;
    }
    __syncthreads();

    // ---- AV: m-split 2, thread owns v-pair vg, 16 q accumulators ----
    int mg = t >> 7;
    int vg = t & 127;
    const float* vbase = value + (b * MMv + mg * 256) * DDv + vg * 2;
    unsigned long long acc[16];
#pragma unroll
    for (int q = 0; q < 16; q++) acc[q] = 0ull;

    for (int m4 = 0; m4 < 256; m4 += 4) {
        float2 v0 = *(const float2*)(vbase + (m4 + 0) * DDv);
        float2 v1 = *(const float2*)(vbase + (m4 + 1) * DDv);
        float2 v2 = *(const float2*)(vbase + (m4 + 2) * DDv);
        float2 v3 = *(const float2*)(vbase + (m4 + 3) * DDv);
        unsigned long long w0 = pk2(v0.x, v0.y);
        unsigned long long w1 = pk2(v1.x, v1.y);
        unsigned long long w2 = pk2(v2.x, v2.y);
        unsigned long long w3 = pk2(v3.x, v3.y);
        int mIdx = mg * 256 + m4;
#pragma unroll
        for (int q = 0; q < 16; q++) {
            float4 p = *(const float4*)&sc[q][mIdx];
            fma2(acc[q], pk2(p.x, p.x), w0);
            fma2(acc[q], pk2(p.y, p.y), w1);
            fma2(acc[q], pk2(p.z, p.z), w2);
            fma2(acc[q], pk2(p.w, p.w), w3);
        }
    }
    __syncthreads();   // all reads of sc done; overlay ps
#pragma unroll
    for (int q = 0; q < 16; q++) ps[mg * 16 + q][vg] = up2(acc[q]);
    __syncthreads();

    // Reduce 2 m-partials, scale, write out: 16q x 128 f2 = 2048 over 256 thr
#pragma unroll
    for (int r = 0; r < 8; r++) {
        int p = t + r * 256;
        int q = p >> 7, v2i = p & 127;
        float2 s0 = ps[q][v2i];
        float2 s1 = ps[16 + q][v2i];
        float iv = inv_s[q];
        ((float2*)out)[(b * NQv + n0 + q) * 128 + v2i] =
            make_float2((s0.x + s1.x) * iv, (s0.y + s1.y) * iv);
    }
}

extern "C" void kernel_launch(void* const* d_in, const int* in_sizes, int n_in,
                              void* d_out, int out_size)
{
    const float* query = (const float*)d_in[0];
    const float* key   = (const float*)d_in[1];
    const float* value = (const float*)d_in[2];
    const float* Wq    = (const float*)d_in[3];
    const float* Wk    = (const float*)d_in[4];
    const float* Wv    = (const float*)d_in[5];
    float* out = (float*)d_out;

    proj_kernel<<<256, 512>>>(query, key, Wq, Wk);
    score_kernel<<<1024, 128>>>(Wv);
    softav_kernel<<<128, 256>>>(value, out);
}

// round 12
// speedup vs baseline: 1.6111x; 1.1252x over previous
#include <cuda_runtime.h>

// Fixed problem dims
#define NB 4
#define NQv 512
#define MMv 512
#define DDv 256
#define HHv 256

// Scratch (device globals: no allocations allowed)
__device__ float    g_q[NB * NQv * HHv];     // projected q, [b*NQ+n][h]
__device__ unsigned g_kTh[NB * HHv * MMv];   // projected k, transposed, packed half2(k,k)
__device__ float    g_sc[NB * NQv * MMv];    // raw scores [b][n][m]

__device__ __forceinline__ float fex2(float x) {
    float y; asm("ex2.approx.f32 %0, %1;" : "=f"(y) : "f"(x)); return y;
}
__device__ __forceinline__ unsigned long long pk2(float a, float b) {
    unsigned long long r; asm("mov.b64 %0, {%1, %2};" : "=l"(r) : "f"(a), "f"(b)); return r;
}
__device__ __forceinline__ void fma2(unsigned long long &d, unsigned long long a, unsigned long long b) {
    asm("fma.rn.f32x2 %0, %1, %2, %0;" : "+l"(d) : "l"(a), "l"(b));
}
__device__ __forceinline__ float2 up2(unsigned long long v) {
    float2 r; asm("mov.b64 {%0, %1}, %2;" : "=f"(r.x), "=f"(r.y) : "l"(v)); return r;
}
__device__ __forceinline__ unsigned packh2(float lo, float hi) {
    unsigned r; asm("cvt.rn.f16x2.f32 %0, %1, %2;" : "=r"(r) : "f"(hi), "f"(lo)); return r;
}
__device__ __forceinline__ unsigned hadd2(unsigned a, unsigned b) {
    unsigned r; asm("add.f16x2 %0, %1, %2;" : "=r"(r) : "r"(a), "r"(b)); return r;
}
__device__ __forceinline__ unsigned htanh2(unsigned a) {
    unsigned r; asm("tanh.approx.f16x2 %0, %1;" : "=r"(r) : "r"(a)); return r;
}
__device__ __forceinline__ unsigned hfma2(unsigned a, unsigned b, unsigned c) {
    unsigned r; asm("fma.rn.f16x2 %0, %1, %2, %3;" : "=r"(r) : "r"(a), "r"(b), "r"(c)); return r;
}
__device__ __forceinline__ void drain2(unsigned p, float &f0, float &f1) {
    unsigned short lo, hi; float a, b;
    asm("mov.b32 {%0, %1}, %2;" : "=h"(lo), "=h"(hi) : "r"(p));
    asm("cvt.f32.f16 %0, %1;" : "=f"(a) : "h"(lo));
    asm("cvt.f32.f16 %0, %1;" : "=f"(b) : "h"(hi));
    f0 += a; f1 += b;
}

// ---------------------------------------------------------------------------
// Combined projection GEMM (R6-proven, frozen): 256 blocks, 64x64 tile,
// 256 threads, 4x4 micro-tile, f32x2 FMAs, double-buffered.
// ---------------------------------------------------------------------------
__global__ __launch_bounds__(256) void proj_kernel(const float* __restrict__ query,
                                                   const float* __restrict__ key,
                                                   const float* __restrict__ Wq,
                                                   const float* __restrict__ Wk)
{
    __shared__ __align__(16) float As[16][68];
    __shared__ __align__(16) float Bs[16][64];

    int bid = blockIdx.x;
    int is_k = bid >> 7;
    int local = bid & 127;
    int row0 = (local >> 2) * 64;
    int col0 = (local & 3) * 64;
    const float* A = is_k ? key : query;
    const float* B = is_k ? Wk : Wq;

    int t = threadIdx.x;
    int tx = t & 15, ty = t >> 4;
    int arow = t >> 2, akq = t & 3;
    int bk = t >> 4, bh = t & 15;

    const float* Aptr = A + (row0 + arow) * DDv + akq * 4;
    const float* Bptr = B + bk * HHv + col0 + bh * 4;

    unsigned long long acc[4][2];
#pragma unroll
    for (int i = 0; i < 4; i++) { acc[i][0] = 0ull; acc[i][1] = 0ull; }

    float4 a_n = *(const float4*)(Aptr);
    float4 b_n = *(const float4*)(Bptr);

    for (int k0 = 0; k0 < DDv; k0 += 16) {
        As[akq * 4 + 0][arow] = a_n.x;
        As[akq * 4 + 1][arow] = a_n.y;
        As[akq * 4 + 2][arow] = a_n.z;
        As[akq * 4 + 3][arow] = a_n.w;
        *(float4*)&Bs[bk][bh * 4] = b_n;
        __syncthreads();

        if (k0 + 16 < DDv) {
            a_n = *(const float4*)(Aptr + k0 + 16);
            b_n = *(const float4*)(Bptr + (k0 + 16) * HHv);
        }

#pragma unroll
        for (int k = 0; k < 16; k++) {
            const unsigned long long* br = (const unsigned long long*)&Bs[k][tx * 4];
            unsigned long long b0 = br[0], b1 = br[1];
#pragma unroll
            for (int i = 0; i < 4; i++) {
                float a = As[k][ty * 4 + i];
                unsigned long long aa = pk2(a, a);
                fma2(acc[i][0], aa, b0);
                fma2(acc[i][1], aa, b1);
            }
        }
        __syncthreads();
    }

#pragma unroll
    for (int i = 0; i < 4; i++) {
        int row = row0 + ty * 4 + i;
        int col = col0 + tx * 4;
        float2 c0 = up2(acc[i][0]);
        float2 c1 = up2(acc[i][1]);
        if (!is_k) {
            *(float4*)(g_q + row * HHv + col) = make_float4(c0.x, c0.y, c1.x, c1.y);
        } else {
            int bb = row >> 9, m = row & 511;
            unsigned* base = g_kTh + (bb * HHv) * MMv + m;
            base[(col + 0) * MMv] = packh2(c0.x, c0.x);
            base[(col + 1) * MMv] = packh2(c0.y, c0.y);
            base[(col + 2) * MMv] = packh2(c1.x, c1.x);
            base[(col + 3) * MMv] = packh2(c1.y, c1.y);
        }
    }
}

// ---------------------------------------------------------------------------
// Score kernel (R9 all-f16x2 body, frozen at MUFU element-rate floor):
// tile (8q x 128m), 128 threads, grid 1024.
// ---------------------------------------------------------------------------
__global__ __launch_bounds__(128) void score_kernel(const float* __restrict__ Wv)
{
    __shared__ __align__(16) uint4 qsh[HHv];
    __shared__ __align__(16) unsigned wsh[HHv];

    int t = threadIdx.x;
    int bid = blockIdx.x;
    int mc = bid & 3;
    int qc = (bid >> 2) & 63;
    int b = bid >> 8;
    int n0 = qc * 8;
    int m = mc * 128 + t;

    {
        const float* qb = g_q + (b * NQv + n0) * HHv + 2 * t;
        float2 r[8];
#pragma unroll
        for (int q = 0; q < 8; q++)
            r[q] = *(const float2*)(qb + q * HHv);
#pragma unroll
        for (int j = 0; j < 2; j++) {
            int h = 2 * t + j;
            float v0 = j ? r[0].y : r[0].x, v1 = j ? r[1].y : r[1].x;
            float v2 = j ? r[2].y : r[2].x, v3 = j ? r[3].y : r[3].x;
            float v4 = j ? r[4].y : r[4].x, v5 = j ? r[5].y : r[5].x;
            float v6 = j ? r[6].y : r[6].x, v7 = j ? r[7].y : r[7].x;
            qsh[h] = make_uint4(packh2(v0, v1), packh2(v2, v3),
                                packh2(v4, v5), packh2(v6, v7));
        }
        float2 wv = *(const float2*)(Wv + 2 * t);
        wsh[2 * t + 0] = packh2(wv.x, wv.x);
        wsh[2 * t + 1] = packh2(wv.y, wv.y);
    }
    __syncthreads();

    float facc[8];
#pragma unroll
    for (int q = 0; q < 8; q++) facc[q] = 0.f;

    const unsigned* kb = g_kTh + (b * HHv) * MMv + m;

    for (int h0 = 0; h0 < HHv; h0 += 8) {
        unsigned acc2[4] = {0u, 0u, 0u, 0u};
#pragma unroll
        for (int hh = 0; hh < 8; hh++) {
            int h = h0 + hh;
            unsigned kk2 = kb[h * MMv];
            uint4 qh = qsh[h];
            unsigned w2 = wsh[h];
            acc2[0] = hfma2(w2, htanh2(hadd2(qh.x, kk2)), acc2[0]);
            acc2[1] = hfma2(w2, htanh2(hadd2(qh.y, kk2)), acc2[1]);
            acc2[2] = hfma2(w2, htanh2(hadd2(qh.z, kk2)), acc2[2]);
            acc2[3] = hfma2(w2, htanh2(hadd2(qh.w, kk2)), acc2[3]);
        }
        drain2(acc2[0], facc[0], facc[1]);
        drain2(acc2[1], facc[2], facc[3]);
        drain2(acc2[2], facc[4], facc[5]);
        drain2(acc2[3], facc[6], facc[7]);
    }

#pragma unroll
    for (int q = 0; q < 8; q++)
        g_sc[(b * NQv + n0 + q) * MMv + m] = facc[q];
}

// ---------------------------------------------------------------------------
// Softmax + AV: 16 queries/block + v-dim split in 2.
// Grid 256 = b(4) x qc(32) x vh(2), 256 threads. Value L2 traffic = 64MB
// (half of R9) while keeping 256 blocks of parallelism (R11's mistake fixed).
// Softmax recomputed per v-half (8K ex2/block - negligible). m-split 4;
// partials overlaid on sc[] (both 32KB).
// ---------------------------------------------------------------------------
__global__ __launch_bounds__(256) void softav_kernel(const float* __restrict__ value,
                                                     float* __restrict__ out)
{
    __shared__ __align__(16) float sc[16][MMv];   // 32KB; overlaid by ps after AV
    __shared__ float inv_s[16];
    float2 (*ps)[16][64] = (float2(*)[16][64])sc; // [4 mg][16 q][64 vg]

    int t = threadIdx.x;
    int bid = blockIdx.x;
    int vh = bid & 1;
    int qc = (bid >> 1) & 31;
    int b = bid >> 6;
    int n0 = qc * 16;
    int w = t >> 5, lane = t & 31;

    // ---- Softmax: warp w handles rows 2w, 2w+1 (16 rows / 8 warps) ----
#pragma unroll
    for (int r = 0; r < 2; r++) {
        int row = 2 * w + r;
        const float* srow = g_sc + (b * NQv + n0 + row) * MMv;
        float vals[16];
        float vmax = -1e30f;
#pragma unroll
        for (int j = 0; j < 16; j++) {
            vals[j] = srow[lane + j * 32];
            vmax = fmaxf(vmax, vals[j]);
        }
#pragma unroll
        for (int o = 16; o > 0; o >>= 1)
            vmax = fmaxf(vmax, __shfl_xor_sync(0xffffffffu, vmax, o));
        float sum = 0.f;
#pragma unroll
        for (int j = 0; j < 16; j++) {
            float p = fex2((vals[j] - vmax) * 1.4426950408889634f);
            sc[row][lane + j * 32] = p;
            sum += p;
        }
#pragma unroll
        for (int o = 16; o > 0; o >>= 1)
            sum += __shfl_xor_sync(0xffffffffu, sum, o);
        if (lane == 0) inv_s[row] = 1.0f / sum;
    }
    __syncthreads();

    // ---- AV: m-split 4, thread owns one v-pair in this block's 128-col half ----
    int mg = t >> 6;          // 0..3
    int vg = t & 63;          // 64 float2 columns per half
    const float* vbase = value + (b * MMv + mg * 128) * DDv + vh * 128 + vg * 2;
    unsigned long long acc[16];
#pragma unroll
    for (int q = 0; q < 16; q++) acc[q] = 0ull;

    for (int m4 = 0; m4 < 128; m4 += 4) {
        float2 v0 = *(const float2*)(vbase + (m4 + 0) * DDv);
        float2 v1 = *(const float2*)(vbase + (m4 + 1) * DDv);
        float2 v2 = *(const float2*)(vbase + (m4 + 2) * DDv);
        float2 v3 = *(const float2*)(vbase + (m4 + 3) * DDv);
        unsigned long long w0 = pk2(v0.x, v0.y);
        unsigned long long w1 = pk2(v1.x, v1.y);
        unsigned long long w2 = pk2(v2.x, v2.y);
        unsigned long long w3 = pk2(v3.x, v3.y);
        int mIdx = mg * 128 + m4;
#pragma unroll
        for (int q = 0; q < 16; q++) {
            float4 p = *(const float4*)&sc[q][mIdx];
            fma2(acc[q], pk2(p.x, p.x), w0);
            fma2(acc[q], pk2(p.y, p.y), w1);
            fma2(acc[q], pk2(p.z, p.z), w2);
            fma2(acc[q], pk2(p.w, p.w), w3);
        }
    }
    __syncthreads();   // all reads of sc done; overlay ps
#pragma unroll
    for (int q = 0; q < 16; q++) ps[mg][q][vg] = up2(acc[q]);
    __syncthreads();

    // Reduce 4 m-partials, scale, write out: 16q x 64 f2 = 1024 over 256 thr
#pragma unroll
    for (int r = 0; r < 4; r++) {
        int p = t + r * 256;
        int q = p >> 6, v2i = p & 63;
        float2 s0 = ps[0][q][v2i];
        float2 s1 = ps[1][q][v2i];
        float2 s2 = ps[2][q][v2i];
        float2 s3 = ps[3][q][v2i];
        float iv = inv_s[q];
        ((float2*)out)[(b * NQv + n0 + q) * 128 + vh * 64 + v2i] =
            make_float2((s0.x + s1.x + s2.x + s3.x) * iv,
                        (s0.y + s1.y + s2.y + s3.y) * iv);
    }
}

extern "C" void kernel_launch(void* const* d_in, const int* in_sizes, int n_in,
                              void* d_out, int out_size)
{
    const float* query = (const float*)d_in[0];
    const float* key   = (const float*)d_in[1];
    const float* value = (const float*)d_in[2];
    const float* Wq    = (const float*)d_in[3];
    const float* Wk    = (const float*)d_in[4];
    const float* Wv    = (const float*)d_in[5];
    float* out = (float*)d_out;

    proj_kernel<<<256, 256>>>(query, key, Wq, Wk);
    score_kernel<<<1024, 128>>>(Wv);
    softav_kernel<<<256, 256>>>(value, out);
}